// round 5
// baseline (speedup 1.0000x reference)
#include <cuda_runtime.h>
#include <stdint.h>

// Geometry fixed by the problem: outputs/masks are [2,1,64,256,256]
#define HH 256
#define WW 256
#define BATCH 2
#define SLICES 128                 // 2*64 independent 2D slices
#define WPR 8                      // 32-bit words per 256-px row
#define NWORDS (HH * WPR)          // 2048 words per slice bitmask
#define NPIX (HH * WW)             // 65536 px per slice
#define NTHREADS 1024              // 32 warps -> occ 50%, double latency hiding

// Per-slice partial sums: [s][0]=intersect, [s][1]=input_area, [s][2]=target_area
__device__ double g_part[SLICES][3];
__device__ unsigned g_ticket = 0;   // reset by the finalizing CTA each run

__global__ __launch_bounds__(NTHREADS, 1)
void bbsd_slice_kernel(const float* __restrict__ outp, const int* __restrict__ mskp,
                       float* __restrict__ out) {
    __shared__ uint32_t mb[NWORDS];            // mask bits (8 KB)
    __shared__ uint32_t buf[2][NWORDS];        // dilation double buffer (16 KB)
    __shared__ uint32_t plane[5][NWORDS / 2];  // bit-planes, one 128-row half (20 KB)
    __shared__ float lut[64];
    __shared__ double red0[32], red1[32], red2[32];
    __shared__ int s_last;

    const int slice = blockIdx.x;
    const size_t base = (size_t)slice * NPIX;
    const int tid = threadIdx.x;
    const int lane = tid & 31;
    const int wid = tid >> 5;

    // weight LUT: dist = (22 - acc)/22, w = 2/(1 + exp(10*dist)), acc in 0..21
    // padded to 64 so index a+extra never needs clamping
    if (tid < 64) {
        int a = tid < 22 ? tid : 21;
        float dist = (22.0f - (float)a) / 22.0f;
        lut[tid] = 2.0f / (1.0f + expf(10.0f * dist));
    }

    // ---- pack mask: coalesced LDG.32 + ballot, deep unroll for MLP ----
    const int* mp = mskp + base;
#pragma unroll 16
    for (int i = 0; i < NPIX / NTHREADS; i++) {
        int idx = i * NTHREADS + tid;
        unsigned wrd = __ballot_sync(0xffffffffu, mp[idx] != 0);
        if (lane == 0) mb[idx >> 5] = wrd;     // idx>>5 warp-uniform
    }
    __syncthreads();

    // thread owns a quarter-row: 2 consecutive words
    const int row = tid >> 2;                  // 0..255
    const int cw0 = (tid & 3) * 2;             // 0,2,4,6
    const int wb = row * WPR + cw0;

    // 5-plane bit-sliced per-pixel counters (acc in 0..21), register-resident
    uint32_t P0[2], P1[2], P2[2], P3[2], P4[2];

    // ---- edge: m & ~(up & down & left & right), zero padded ----
#pragma unroll
    for (int j = 0; j < 2; j++) {
        int cw = cw0 + j, gw = wb + j;
        uint32_t m  = mb[gw];
        uint32_t up = row            ? mb[gw - WPR] : 0u;
        uint32_t dn = (row < HH - 1) ? mb[gw + WPR] : 0u;
        uint32_t pv = cw             ? mb[gw - 1]   : 0u;
        uint32_t nx = (cw < WPR - 1) ? mb[gw + 1]   : 0u;
        uint32_t lf = (m << 1) | (pv >> 31);
        uint32_t rt = (m >> 1) | (nx << 31);
        uint32_t e = m & ~(up & dn & lf & rt);
        buf[0][gw] = e;
        P0[j] = e; P1[j] = 0u; P2[j] = 0u; P3[j] = 0u; P4[j] = 0u;
    }
    __syncthreads();

    // ---- cascaded 3x3 OR-dilations with saturation early-exit ----
    // Once the dilation mask is all-ones, every remaining round adds +1
    // uniformly -> fold into 'extra' applied at LUT-lookup time.
    int extra = 0;
    int sb = 0;
    for (int r = 1; r <= 20; r++) {
        const uint32_t* src = buf[sb];
        uint32_t* dst = buf[sb ^ 1];
        uint32_t va[4];
#pragma unroll
        for (int k = 0; k < 4; k++) {
            int cw = cw0 + k - 1;
            uint32_t v = 0u;
            if (cw >= 0 && cw < WPR) {
                int gw = row * WPR + cw;
                v = src[gw];
                if (row)          v |= src[gw - WPR];
                if (row < HH - 1) v |= src[gw + WPR];
            }
            va[k] = v;
        }
        uint32_t allw = 0xffffffffu;
#pragma unroll
        for (int j = 0; j < 2; j++) {
            uint32_t c = va[j + 1];
            uint32_t nw = c | (c << 1) | (va[j] >> 31) | (c >> 1) | (va[j + 2] << 31);
            dst[wb + j] = nw;
            allw &= nw;
            uint32_t cy = nw, t;               // ripple-carry +1 where nw set
            t = P0[j] & cy; P0[j] ^= cy; cy = t;
            t = P1[j] & cy; P1[j] ^= cy; cy = t;
            t = P2[j] & cy; P2[j] ^= cy; cy = t;
            t = P3[j] & cy; P3[j] ^= cy; cy = t;
            P4[j] ^= cy;
        }
        sb ^= 1;
        if (__syncthreads_and(allw == 0xffffffffu)) { extra = 20 - r; break; }
    }

    // ---- decode + weighted sums, two 128-row stages, coalesced LDG.128 ----
    float s_ia = 0.f, s_in = 0.f, s_ta = 0.f;
    for (int half = 0; half < 2; half++) {
        __syncthreads();
        if ((row >> 7) == half) {
            int lw = (row & 127) * WPR + cw0;
#pragma unroll
            for (int j = 0; j < 2; j++) {
                plane[0][lw + j] = P0[j];
                plane[1][lw + j] = P1[j];
                plane[2][lw + j] = P2[j];
                plane[3][lw + j] = P3[j];
                plane[4][lw + j] = P4[j];
            }
        }
        __syncthreads();

        const float4* op4 = reinterpret_cast<const float4*>(outp + base + (size_t)half * (NPIX / 2));
        const uint32_t* mbh = mb + half * (NWORDS / 2);
#pragma unroll 8
        for (int k = 0; k < 8; k++) {
            int g = k * NTHREADS + tid;        // float4 group; lanes consecutive
            float4 v = op4[g];
            int lw = g >> 3;
            int i0 = (g & 7) * 4;
            uint32_t p0 = plane[0][lw];
            uint32_t p1 = plane[1][lw];
            uint32_t p2 = plane[2][lw];
            uint32_t p3 = plane[3][lw];
            uint32_t p4 = plane[4][lw];
            uint32_t qm = mbh[lw] >> i0;
            float vv[4] = {v.x, v.y, v.z, v.w};

            // fast path: all 32 px in this word share one acc value
            bool uni = ((p0 + 1u) <= 1u) & ((p1 + 1u) <= 1u) & ((p2 + 1u) <= 1u)
                     & ((p3 + 1u) <= 1u) & ((p4 + 1u) <= 1u);
            if (uni) {
                unsigned a = (p0 & 1u) | ((p1 & 1u) << 1) | ((p2 & 1u) << 2)
                           | ((p3 & 1u) << 3) | ((p4 & 1u) << 4);
                float w = lut[a + extra];
                float acc4 = 0.f, accm = 0.f;
#pragma unroll
                for (int e = 0; e < 4; e++) {
                    acc4 += vv[e];
                    accm += ((qm >> e) & 1u) ? vv[e] : 0.f;
                }
                s_ia += w * acc4;
                s_in += w * accm;
                s_ta += w * (float)__popc(qm & 0xFu);
            } else {
                uint32_t q0 = p0 >> i0, q1 = p1 >> i0, q2 = p2 >> i0,
                         q3 = p3 >> i0, q4 = p4 >> i0;
#pragma unroll
                for (int e = 0; e < 4; e++) {
                    unsigned a = ((q0 >> e) & 1u)
                               | (((q1 >> e) & 1u) << 1)
                               | (((q2 >> e) & 1u) << 2)
                               | (((q3 >> e) & 1u) << 3)
                               | (((q4 >> e) & 1u) << 4);
                    float w = lut[a + extra];
                    float fm = (float)((qm >> e) & 1u);
                    float f = vv[e] * w;
                    s_ia += f;
                    s_in += f * fm;
                    s_ta += w * fm;
                }
            }
        }
    }

    // ---- reduce to per-slice partials ----
    double d0 = (double)s_in, d1 = (double)s_ia, d2 = (double)s_ta;
#pragma unroll
    for (int o = 16; o > 0; o >>= 1) {
        d0 += __shfl_down_sync(0xffffffffu, d0, o);
        d1 += __shfl_down_sync(0xffffffffu, d1, o);
        d2 += __shfl_down_sync(0xffffffffu, d2, o);
    }
    if (lane == 0) { red0[wid] = d0; red1[wid] = d1; red2[wid] = d2; }
    __syncthreads();
    if (wid == 0) {
        double a0 = red0[lane];
        double a1 = red1[lane];
        double a2 = red2[lane];
#pragma unroll
        for (int o = 16; o > 0; o >>= 1) {
            a0 += __shfl_down_sync(0xffffffffu, a0, o);
            a1 += __shfl_down_sync(0xffffffffu, a1, o);
            a2 += __shfl_down_sync(0xffffffffu, a2, o);
        }
        if (lane == 0) {
            g_part[slice][0] = a0;
            g_part[slice][1] = a1;
            g_part[slice][2] = a2;
        }
    }

    // ---- fused finalize: last-arriving CTA computes the scalar loss ----
    if (tid == 0) {
        __threadfence();                              // publish g_part writes
        unsigned t = atomicAdd(&g_ticket, 1u);
        s_last = (t == SLICES - 1);
    }
    __syncthreads();
    if (s_last && wid == 0) {
        __threadfence();                              // see all g_part writes
        double loss = 0.0;
#pragma unroll
        for (int b = 0; b < BATCH; b++) {
            double i0 = g_part[b * 64 + lane][0] + g_part[b * 64 + 32 + lane][0];
            double a0 = g_part[b * 64 + lane][1] + g_part[b * 64 + 32 + lane][1];
            double t0 = g_part[b * 64 + lane][2] + g_part[b * 64 + 32 + lane][2];
#pragma unroll
            for (int o = 16; o > 0; o >>= 1) {
                i0 += __shfl_down_sync(0xffffffffu, i0, o);
                a0 += __shfl_down_sync(0xffffffffu, a0, o);
                t0 += __shfl_down_sync(0xffffffffu, t0, o);
            }
            if (lane == 0)
                loss += (t0 == 0.0) ? 0.0 : (1.0 - 2.0 * i0 / (a0 + t0 + 2.0e-6));
        }
        if (lane == 0) {
            out[0] = (float)(loss * 0.5);             // mean over BATCH=2
            g_ticket = 0;                             // reset for next graph replay
        }
    }
}

extern "C" void kernel_launch(void* const* d_in, const int* in_sizes, int n_in,
                              void* d_out, int out_size) {
    const float* outputs = (const float*)d_in[0];  // float32 [2,1,64,256,256]
    const int*   masks   = (const int*)d_in[1];    // int32   [2,1,64,256,256]
    float* out = (float*)d_out;

    bbsd_slice_kernel<<<SLICES, NTHREADS>>>(outputs, masks, out);
}

// round 6
// speedup vs baseline: 1.0790x; 1.0790x over previous
#include <cuda_runtime.h>
#include <stdint.h>

// Geometry fixed by the problem: outputs/masks are [2,1,64,256,256]
#define HH 256
#define WW 256
#define BATCH 2
#define SLICES 128                 // 2*64 independent 2D slices
#define WPR 8                      // 32-bit words per 256-px row
#define NWORDS (HH * WPR)          // 2048 words per slice bitmask
#define NPIX (HH * WW)             // 65536 px per slice
#define NTHREADS 1024

// Per-slice partial sums: [s][0]=intersect, [s][1]=input_area, [s][2]=target_area
__device__ double g_part[SLICES][3];
__device__ unsigned g_ticket = 0;

__global__ __launch_bounds__(NTHREADS, 1)
void bbsd_slice_kernel(const float* __restrict__ outp, const int* __restrict__ mskp,
                       float* __restrict__ out) {
    __shared__ uint32_t mb[NWORDS];          // mask bits (8 KB)
    __shared__ uint32_t eb[NWORDS];          // edge bits (8 KB)
    __shared__ uint32_t scratch[5 * 1024];   // cascade bufs (16K) / plane spill (20K), aliased
    __shared__ int      wb_s[1024];          // per-word base index (one half)  (4 KB)
    __shared__ uint32_t hm_s[1024];          // per-word K==ktop bitmask        (4 KB)
    __shared__ float lut[64];
    __shared__ double red0[32], red1[32], red2[32];
    __shared__ int s_last;

    const int slice = blockIdx.x;
    const size_t base = (size_t)slice * NPIX;
    const int tid = threadIdx.x;
    const int lane = tid & 31;
    const int wid = tid >> 5;

    // weight LUT: acc in 0..21; dist=(22-acc)/22; w=2/(1+exp(10*dist)); padded
    if (tid < 64) {
        int a = tid < 22 ? tid : 21;
        float dist = (22.0f - (float)a) / 22.0f;
        lut[tid] = 2.0f / (1.0f + expf(10.0f * dist));
    }

    // ---- pack mask: int4 LDG.128, nibble build, 3x shfl-OR within 8-lane groups ----
    const int4* mp4 = reinterpret_cast<const int4*>(mskp + base);
#pragma unroll
    for (int i = 0; i < NPIX / (NTHREADS * 4); i++) {   // 16 iters
        int g = i * NTHREADS + tid;
        int4 v = mp4[g];
        unsigned nib = (v.x != 0 ? 1u : 0u) | (v.y != 0 ? 2u : 0u)
                     | (v.z != 0 ? 4u : 0u) | (v.w != 0 ? 8u : 0u);
        unsigned w = nib << ((lane & 7) * 4);
        w |= __shfl_xor_sync(0xffffffffu, w, 1);
        w |= __shfl_xor_sync(0xffffffffu, w, 2);
        w |= __shfl_xor_sync(0xffffffffu, w, 4);
        if ((lane & 7) == 0) mb[g >> 3] = w;
    }
    __syncthreads();

    // thread owns a quarter-row: 2 consecutive words (word index = 2*tid)
    const int row = tid >> 2;
    const int cw0 = (tid & 3) * 2;
    const int wb = row * WPR + cw0;

    // 5-plane bit-sliced coverage counters K (rounds only; edge kept separate)
    uint32_t P0[2], P1[2], P2[2], P3[2], P4[2];

    // ---- edge: m & ~(up & down & left & right), zero padded ----
#pragma unroll
    for (int j = 0; j < 2; j++) {
        int cw = cw0 + j, gw = wb + j;
        uint32_t m  = mb[gw];
        uint32_t up = row            ? mb[gw - WPR] : 0u;
        uint32_t dn = (row < HH - 1) ? mb[gw + WPR] : 0u;
        uint32_t pv = cw             ? mb[gw - 1]   : 0u;
        uint32_t nx = (cw < WPR - 1) ? mb[gw + 1]   : 0u;
        uint32_t lf = (m << 1) | (pv >> 31);
        uint32_t rt = (m >> 1) | (nx << 31);
        uint32_t e = m & ~(up & dn & lf & rt);
        scratch[gw] = e;                 // dilation src buffer 0
        eb[gw] = e;
        P0[j] = 0u; P1[j] = 0u; P2[j] = 0u; P3[j] = 0u; P4[j] = 0u;
    }
    __syncthreads();

    // ---- cascaded 3x3 OR-dilations with saturation early-exit ----
    // After the mask saturates to all-ones, remaining rounds add +1 uniformly
    // -> folded into 'extra' at LUT-index time.
    int extra = 0;
    int sb = 0;
    for (int r = 1; r <= 20; r++) {
        const uint32_t* src = scratch + sb * 2048;
        uint32_t* dst = scratch + (sb ^ 1) * 2048;
        uint32_t va[4];
#pragma unroll
        for (int k = 0; k < 4; k++) {
            int cw = cw0 + k - 1;
            uint32_t v = 0u;
            if (cw >= 0 && cw < WPR) {
                int gw = row * WPR + cw;
                v = src[gw];
                if (row)          v |= src[gw - WPR];
                if (row < HH - 1) v |= src[gw + WPR];
            }
            va[k] = v;
        }
        uint32_t allw = 0xffffffffu;
#pragma unroll
        for (int j = 0; j < 2; j++) {
            uint32_t c = va[j + 1];
            uint32_t nw = c | (c << 1) | (va[j] >> 31) | (c >> 1) | (va[j + 2] << 31);
            dst[wb + j] = nw;
            allw &= nw;
            uint32_t cy = nw, t;         // ripple-carry +1 where covered
            t = P0[j] & cy; P0[j] ^= cy; cy = t;
            t = P1[j] & cy; P1[j] ^= cy; cy = t;
            t = P2[j] & cy; P2[j] ^= cy; cy = t;
            t = P3[j] & cy; P3[j] ^= cy; cy = t;
            P4[j] ^= cy;
        }
        sb ^= 1;
        if (__syncthreads_and(allw == 0xffffffffu)) { extra = 20 - r; break; }
    }

    // ---- per-half: spill planes + per-word decode metadata, then decode ----
    float s_ia = 0.f, s_in = 0.f, s_ta = 0.f;
    for (int half = 0; half < 2; half++) {
        __syncthreads();   // planes/meta of previous half fully consumed
        if ((row >> 7) == half) {
            int lw = ((row & 127) * WPR + cw0);      // local word index in half
#pragma unroll
            for (int j = 0; j < 2; j++) {
                uint32_t p0 = P0[j], p1 = P1[j], p2 = P2[j], p3 = P3[j], p4 = P4[j];
                scratch[0 * 1024 + lw + j] = p0;     // plane spill (aliases dead bufs)
                scratch[1 * 1024 + lw + j] = p1;
                scratch[2 * 1024 + lw + j] = p2;
                scratch[3 * 1024 + lw + j] = p3;
                scratch[4 * 1024 + lw + j] = p4;
                // k_top = K of bit 31
                unsigned kt = ((p0 >> 31) & 1u) | (((p1 >> 31) & 1u) << 1)
                            | (((p2 >> 31) & 1u) << 2) | (((p3 >> 31) & 1u) << 3)
                            | (((p4 >> 31) & 1u) << 4);
                uint32_t mhi = ((kt & 1u)  ? p0 : ~p0) & ((kt & 2u)  ? p1 : ~p1)
                             & ((kt & 4u)  ? p2 : ~p2) & ((kt & 8u)  ? p3 : ~p3)
                             & ((kt & 16u) ? p4 : ~p4);
                uint32_t mlo = 0u;
                if (kt) {
                    unsigned kl = kt - 1u;
                    mlo = ((kl & 1u)  ? p0 : ~p0) & ((kl & 2u)  ? p1 : ~p1)
                        & ((kl & 4u)  ? p2 : ~p2) & ((kl & 8u)  ? p3 : ~p3)
                        & ((kl & 16u) ? p4 : ~p4);
                }
                bool valid = (mhi | mlo) == 0xffffffffu;
                wb_s[lw + j] = valid ? ((int)kt - 1 + extra) : -100;
                hm_s[lw + j] = mhi;
            }
        }
        __syncthreads();

        const float4* op4 = reinterpret_cast<const float4*>(outp + base + (size_t)half * (NPIX / 2));
#pragma unroll
        for (int k = 0; k < 8; k++) {
            int g = k * NTHREADS + tid;              // float4 group in this half
            float4 v = op4[g];
            int lw = g >> 3;
            int i0 = (g & 7) * 4;
            int wbase = wb_s[lw];
            uint32_t qm = mb[half * 1024 + lw] >> i0;
            uint32_t qe = eb[half * 1024 + lw] >> i0;
            float vv[4] = {v.x, v.y, v.z, v.w};
            if (wbase != -100) {
                uint32_t qh = hm_s[lw] >> i0;
#pragma unroll
                for (int e = 0; e < 4; e++) {
                    int idx = wbase + (int)((qh >> e) & 1u) + (int)((qe >> e) & 1u);
                    float w = lut[idx];
                    float f = vv[e] * w;
                    s_ia += f;
                    if ((qm >> e) & 1u) { s_in += f; s_ta += w; }
                }
            } else {
                uint32_t q0 = scratch[0 * 1024 + lw] >> i0;
                uint32_t q1 = scratch[1 * 1024 + lw] >> i0;
                uint32_t q2 = scratch[2 * 1024 + lw] >> i0;
                uint32_t q3 = scratch[3 * 1024 + lw] >> i0;
                uint32_t q4 = scratch[4 * 1024 + lw] >> i0;
#pragma unroll
                for (int e = 0; e < 4; e++) {
                    unsigned a = ((q0 >> e) & 1u)
                               | (((q1 >> e) & 1u) << 1)
                               | (((q2 >> e) & 1u) << 2)
                               | (((q3 >> e) & 1u) << 3)
                               | (((q4 >> e) & 1u) << 4);
                    a += ((qe >> e) & 1u) + extra;
                    float w = lut[a];
                    float f = vv[e] * w;
                    s_ia += f;
                    if ((qm >> e) & 1u) { s_in += f; s_ta += w; }
                }
            }
        }
    }

    // ---- reduce to per-slice partials ----
    double d0 = (double)s_in, d1 = (double)s_ia, d2 = (double)s_ta;
#pragma unroll
    for (int o = 16; o > 0; o >>= 1) {
        d0 += __shfl_down_sync(0xffffffffu, d0, o);
        d1 += __shfl_down_sync(0xffffffffu, d1, o);
        d2 += __shfl_down_sync(0xffffffffu, d2, o);
    }
    if (lane == 0) { red0[wid] = d0; red1[wid] = d1; red2[wid] = d2; }
    __syncthreads();
    if (wid == 0) {
        double a0 = red0[lane];
        double a1 = red1[lane];
        double a2 = red2[lane];
#pragma unroll
        for (int o = 16; o > 0; o >>= 1) {
            a0 += __shfl_down_sync(0xffffffffu, a0, o);
            a1 += __shfl_down_sync(0xffffffffu, a1, o);
            a2 += __shfl_down_sync(0xffffffffu, a2, o);
        }
        if (lane == 0) {
            g_part[slice][0] = a0;
            g_part[slice][1] = a1;
            g_part[slice][2] = a2;
        }
    }

    // ---- fused finalize: last-arriving CTA computes the scalar loss ----
    if (tid == 0) {
        __threadfence();
        unsigned t = atomicAdd(&g_ticket, 1u);
        s_last = (t == SLICES - 1);
    }
    __syncthreads();
    if (s_last && wid == 0) {
        __threadfence();
        double loss = 0.0;
#pragma unroll
        for (int b = 0; b < BATCH; b++) {
            double i0 = g_part[b * 64 + lane][0] + g_part[b * 64 + 32 + lane][0];
            double a0 = g_part[b * 64 + lane][1] + g_part[b * 64 + 32 + lane][1];
            double t0 = g_part[b * 64 + lane][2] + g_part[b * 64 + 32 + lane][2];
#pragma unroll
            for (int o = 16; o > 0; o >>= 1) {
                i0 += __shfl_down_sync(0xffffffffu, i0, o);
                a0 += __shfl_down_sync(0xffffffffu, a0, o);
                t0 += __shfl_down_sync(0xffffffffu, t0, o);
            }
            if (lane == 0)
                loss += (t0 == 0.0) ? 0.0 : (1.0 - 2.0 * i0 / (a0 + t0 + 2.0e-6));
        }
        if (lane == 0) {
            out[0] = (float)(loss * 0.5);
            g_ticket = 0;
        }
    }
}

extern "C" void kernel_launch(void* const* d_in, const int* in_sizes, int n_in,
                              void* d_out, int out_size) {
    const float* outputs = (const float*)d_in[0];  // float32 [2,1,64,256,256]
    const int*   masks   = (const int*)d_in[1];    // int32   [2,1,64,256,256]
    float* out = (float*)d_out;

    bbsd_slice_kernel<<<SLICES, NTHREADS>>>(outputs, masks, out);
}